// round 16
// baseline (speedup 1.0000x reference)
#include <cuda_runtime.h>
#include <cuda_fp16.h>
#include <cstdint>

#define DIMC   1024
#define HEADS  16
#define NTOK   49
#define BATCH  1024
#define MROWS  (BATCH * NTOK)   // 50176
#define SCALE  0.125f

// ---------------- half scratch ----------------
__device__ __half g_A[(size_t)MROWS * DIMC];
__device__ __half g_B[(size_t)MROWS * DIMC];
__device__ __half g_Q[(size_t)MROWS * DIMC];
__device__ __half g_K[(size_t)MROWS * DIMC];
__device__ __half g_V[(size_t)MROWS * DIMC];
__device__ __half g_Wh[4 * (size_t)DIMC * DIMC];
__device__ float  g_bias[HEADS * NTOK * NTOK];

// ---------------- fused conversion: inputs + weights + bias table ----------------
__global__ void f2h_all(const float* __restrict__ a, const float* __restrict__ b,
                        const float* __restrict__ w0, const float* __restrict__ w1,
                        const float* __restrict__ w2, const float* __restrict__ w3,
                        const float* __restrict__ bt, const int* __restrict__ ri) {
    const int n4 = MROWS * DIMC / 4;
    int i = blockIdx.x * blockDim.x + threadIdx.x;
    int stride = gridDim.x * blockDim.x;
    for (int t = i; t < n4; t += stride) {
        float4 v = ((const float4*)a)[t];
        __half2 h0 = __floats2half2_rn(v.x, v.y), h1 = __floats2half2_rn(v.z, v.w);
        ((uint2*)g_A)[t] = make_uint2(*(uint32_t*)&h0, *(uint32_t*)&h1);
        v = ((const float4*)b)[t];
        h0 = __floats2half2_rn(v.x, v.y); h1 = __floats2half2_rn(v.z, v.w);
        ((uint2*)g_B)[t] = make_uint2(*(uint32_t*)&h0, *(uint32_t*)&h1);
    }
    const float* srcs[4] = {w0, w1, w2, w3};
    const int w4 = DIMC * DIMC / 4;
#pragma unroll
    for (int m = 0; m < 4; ++m) {
        const float4* src = (const float4*)srcs[m];
        uint2* dst = (uint2*)(g_Wh + (size_t)m * DIMC * DIMC);
        for (int t = i; t < w4; t += stride) {
            float4 v = src[t];
            __half2 h0 = __floats2half2_rn(v.x, v.y), h1 = __floats2half2_rn(v.z, v.w);
            dst[t] = make_uint2(*(uint32_t*)&h0, *(uint32_t*)&h1);
        }
    }
    for (int t = i; t < NTOK * NTOK; t += stride) {
        int idx = ri[t] * HEADS;
#pragma unroll
        for (int h = 0; h < HEADS; ++h)
            g_bias[h * (NTOK * NTOK) + t] = bt[idx + h];
    }
}

// ---------------- asm helpers ----------------
__device__ __forceinline__ void cp_async16(uint32_t saddr, const void* g) {
    asm volatile("cp.async.cg.shared.global [%0], [%1], 16;\n" :: "r"(saddr), "l"(g) : "memory");
}
__device__ __forceinline__ void cp_commit() { asm volatile("cp.async.commit_group;\n" ::: "memory"); }
__device__ __forceinline__ void cp_wait1() { asm volatile("cp.async.wait_group 1;\n" ::: "memory"); }
__device__ __forceinline__ void cp_wait0() { asm volatile("cp.async.wait_group 0;\n" ::: "memory"); }

__device__ __forceinline__ void mma_f16(float c[4], uint32_t a0, uint32_t a1, uint32_t a2,
                                        uint32_t a3, uint32_t b0, uint32_t b1) {
    asm volatile(
        "mma.sync.aligned.m16n8k16.row.col.f32.f16.f16.f32 "
        "{%0,%1,%2,%3}, {%4,%5,%6,%7}, {%8,%9}, {%0,%1,%2,%3};\n"
        : "+f"(c[0]), "+f"(c[1]), "+f"(c[2]), "+f"(c[3])
        : "r"(a0), "r"(a1), "r"(a2), "r"(a3), "r"(b0), "r"(b1));
}

__device__ __forceinline__ void ldsm_x4(uint32_t& r0, uint32_t& r1, uint32_t& r2, uint32_t& r3,
                                        uint32_t addr) {
    asm volatile("ldmatrix.sync.aligned.m8n8.x4.shared.b16 {%0,%1,%2,%3}, [%4];"
                 : "=r"(r0), "=r"(r1), "=r"(r2), "=r"(r3) : "r"(addr));
}
__device__ __forceinline__ void ldsm_x4_t(uint32_t& r0, uint32_t& r1, uint32_t& r2, uint32_t& r3,
                                          uint32_t addr) {
    asm volatile("ldmatrix.sync.aligned.m8n8.x4.trans.shared.b16 {%0,%1,%2,%3}, [%4];"
                 : "=r"(r0), "=r"(r1), "=r"(r2), "=r"(r3) : "r"(addr));
}

// ---------------- FP16 GEMM core (proven shape, FROZEN) ----------------
#define BM 128
#define BN 128
#define BKH 64
#define NKT (DIMC / BKH)           // 16
#define TILE_A (BM * 128)          // 16384 B
#define SLOT (2 * TILE_A)
#define SMEMSZ (3 * SLOT)          // 98304 B

__device__ __forceinline__ void gemm_core(
    const __half* __restrict__ X, const __half* __restrict__ W,
    const float* __restrict__ bias, float* __restrict__ Yf, __half* __restrict__ Yh,
    int m0, int n0, uint8_t* smem)
{
    const int tid = threadIdx.x, wid = tid >> 5, lane = tid & 31;
    const int wm = wid >> 2, wn = wid & 3;
    const uint32_t sbase = (uint32_t)__cvta_generic_to_shared(smem);

    float acc[4][4][4];
#pragma unroll
    for (int a = 0; a < 4; ++a)
#pragma unroll
        for (int b = 0; b < 4; ++b)
#pragma unroll
            for (int c = 0; c < 4; ++c) acc[a][b][c] = 0.f;

    const int lane_r = lane & 15;
    const int halfA  = lane >> 4;
    const int swA    = lane_r & 7;
    uint32_t offA[4];
#pragma unroll
    for (int mi = 0; mi < 4; ++mi)
        offA[mi] = (uint32_t)((wm * 64 + mi * 16 + lane_r) * 128);

    const int quad = lane >> 3;
    const int swB  = lane & 7;
    const int gselB = quad & 1;
    uint32_t offB[2];
#pragma unroll
    for (int pi = 0; pi < 2; ++pi)
        offB[pi] = (uint32_t)((wn * 32 + (2 * pi + (quad >> 1)) * 8 + (lane & 7)) * 128);

    const int row = tid >> 1;
    const int g0 = (tid & 1) * 4;
    const int swr = row & 7;
    auto load_stage = [&](int slot, int kt) {
        const __half* xa = X + (size_t)(m0 + row) * DIMC + kt * BKH;
        const __half* xb = W + (size_t)(n0 + row) * DIMC + kt * BKH;
        uint32_t sa = sbase + slot * SLOT + row * 128;
        uint32_t sb = sa + TILE_A;
#pragma unroll
        for (int q = 0; q < 4; ++q) {
            int g = g0 + q;
            uint32_t off = (uint32_t)((g ^ swr) << 4);
            cp_async16(sa + off, xa + g * 8);
            cp_async16(sb + off, xb + g * 8);
        }
        cp_commit();
    };

    load_stage(0, 0);
    load_stage(1, 1);

    const int r8 = lane >> 2, cp2 = (lane & 3) * 2;

    for (int kt = 0; kt < NKT; ++kt) {
        cp_wait1();
        __syncthreads();
        if (kt + 2 < NKT) load_stage((kt + 2) % 3, kt + 2);

        const uint32_t baseA = sbase + (kt % 3) * SLOT;
        const uint32_t baseB = baseA + TILE_A;
#pragma unroll
        for (int ks = 0; ks < 4; ++ks) {
            uint32_t a[4][4], b[2][4];
            const uint32_t gA = (uint32_t)(((ks * 2 + halfA) ^ swA) << 4);
            const uint32_t gB = (uint32_t)(((ks * 2 + gselB) ^ swB) << 4);
#pragma unroll
            for (int mi = 0; mi < 4; ++mi)
                ldsm_x4(a[mi][0], a[mi][1], a[mi][2], a[mi][3], baseA + offA[mi] + gA);
#pragma unroll
            for (int pi = 0; pi < 2; ++pi)
                ldsm_x4(b[pi][0], b[pi][1], b[pi][2], b[pi][3], baseB + offB[pi] + gB);
#pragma unroll
            for (int mi = 0; mi < 4; ++mi) {
                mma_f16(acc[mi][0], a[mi][0], a[mi][1], a[mi][2], a[mi][3], b[0][0], b[0][1]);
                mma_f16(acc[mi][1], a[mi][0], a[mi][1], a[mi][2], a[mi][3], b[0][2], b[0][3]);
                mma_f16(acc[mi][2], a[mi][0], a[mi][1], a[mi][2], a[mi][3], b[1][0], b[1][1]);
                mma_f16(acc[mi][3], a[mi][0], a[mi][1], a[mi][2], a[mi][3], b[1][2], b[1][3]);
            }
        }
    }

#pragma unroll
    for (int mi = 0; mi < 4; ++mi) {
        int r = m0 + wm * 64 + mi * 16 + r8;
#pragma unroll
        for (int ni = 0; ni < 4; ++ni) {
            int cc = n0 + wn * 32 + ni * 8 + cp2;
            float b0 = bias[cc], b1 = bias[cc + 1];
            float v0 = acc[mi][ni][0] + b0, v1 = acc[mi][ni][1] + b1;
            float v2 = acc[mi][ni][2] + b0, v3 = acc[mi][ni][3] + b1;
            if (Yf) {
                *(float2*)&Yf[(size_t)r * DIMC + cc]       = make_float2(v0, v1);
                *(float2*)&Yf[(size_t)(r + 8) * DIMC + cc] = make_float2(v2, v3);
            } else {
                __half2 h0 = __floats2half2_rn(v0, v1);
                __half2 h1 = __floats2half2_rn(v2, v3);
                *(__half2*)&Yh[(size_t)r * DIMC + cc]       = h0;
                *(__half2*)&Yh[(size_t)(r + 8) * DIMC + cc] = h1;
            }
        }
    }
}

__global__ __launch_bounds__(256, 2) void gemm_qkv(
    const float* __restrict__ bq, const float* __restrict__ bk, const float* __restrict__ bv)
{
    extern __shared__ __align__(128) uint8_t smem[];
    const int z = blockIdx.z;
    const __half* X = (z == 0) ? g_A : g_B;
    const __half* W = g_Wh + (size_t)z * DIMC * DIMC;
    __half* Yh = (z == 0) ? g_Q : (z == 1) ? g_K : g_V;
    const float* bias = (z == 0) ? bq : (z == 1) ? bk : bv;
    gemm_core(X, W, bias, nullptr, Yh, blockIdx.y * BM, blockIdx.x * BN, smem);
}

__global__ __launch_bounds__(256, 2) void gemm_o(
    const float* __restrict__ bo, float* __restrict__ out)
{
    extern __shared__ __align__(128) uint8_t smem[];
    gemm_core(g_B, g_Wh + 3 * (size_t)DIMC * DIMC, bo, out, nullptr,
              blockIdx.y * BM, blockIdx.x * BN, smem);
}

// ---------------- attention v4: 4 heads/CTA, 2 warps/head, 32 q-rows/warp ----------------
#define HPC 4                          // heads per CTA
#define HTILE 8192                     // 64 rows x 128B per head tile
#define ATTN_SMEM (3 * HPC * HTILE)    // 98304 B

__global__ __launch_bounds__(256, 2) void attn_mma() {
    extern __shared__ __align__(128) uint8_t smemA[];

    const int b = blockIdx.x, h0 = blockIdx.y * HPC;
    const int tid = threadIdx.x, warp = tid >> 5, lane = tid & 31;
    const size_t bbase = (size_t)(b * NTOK) * DIMC;

    const uint32_t sb = (uint32_t)__cvta_generic_to_shared(smemA);
    const uint32_t kOff = HPC * HTILE, vOff = 2 * HPC * HTILE;

    // async loads: 4 heads x 49 rows x 8 granules for Q,K,V
    for (int t = tid; t < HPC * NTOK * 8; t += 256) {
        int hh = t / (NTOK * 8), rem = t % (NTOK * 8);
        int r = rem >> 3, g = rem & 7;
        uint32_t off = (uint32_t)(hh * HTILE + r * 128 + ((g ^ (r & 7)) << 4));
        size_t gsrc = bbase + (size_t)r * DIMC + (h0 + hh) * 64 + g * 8;
        cp_async16(sb + off,        &g_Q[gsrc]);
        cp_async16(sb + kOff + off, &g_K[gsrc]);
        cp_async16(sb + vOff + off, &g_V[gsrc]);
    }
    // zero V pad rows (disjoint from async targets)
    for (int t = tid; t < HPC * 15 * 8; t += 256) {
        int hh = t / (15 * 8), rem = t % (15 * 8);
        int r = NTOK + (rem >> 3), g = rem & 7;
        uint32_t off = (uint32_t)(hh * HTILE + r * 128 + ((g ^ (r & 7)) << 4));
        *(uint4*)(smemA + vOff + off) = make_uint4(0, 0, 0, 0);
    }
    cp_commit();
    cp_wait0();
    __syncthreads();

    const int hh = warp >> 1;               // head within CTA
    const int qbase = (warp & 1) * 32;      // this warp's 32 q-rows
    const uint32_t qb = sb + hh * HTILE;
    const uint32_t kb = sb + kOff + hh * HTILE;
    const uint32_t vb = sb + vOff + hh * HTILE;
    const size_t hb = bbase + (h0 + hh) * 64;

    const int lane_r = lane & 15, halfA = lane >> 4;
    const int quad = lane >> 3, gsel = quad & 1, rsel = quad >> 1;
    const int r8 = lane >> 2, cp2 = (lane & 3) * 2;
    const int swA = lane_r & 7, sw8 = lane & 7;

    // ---- QK^T: 32 q-rows x 64 j ----
    float acc[2][8][4];
#pragma unroll
    for (int mf = 0; mf < 2; ++mf)
#pragma unroll
        for (int nt = 0; nt < 8; ++nt)
#pragma unroll
            for (int c = 0; c < 4; ++c) acc[mf][nt][c] = 0.f;

    uint32_t aRow[2];
    aRow[0] = qb + (uint32_t)((qbase + lane_r) * 128);
    aRow[1] = qb + (uint32_t)((qbase + 16 + lane_r) * 128);
    uint32_t bRowOff[4];
#pragma unroll
    for (int pj = 0; pj < 4; ++pj)
        bRowOff[pj] = kb + (uint32_t)((16 * pj + rsel * 8 + sw8) * 128);

#pragma unroll
    for (int ks = 0; ks < 4; ++ks) {
        const uint32_t gA = (uint32_t)(((ks * 2 + halfA) ^ swA) << 4);
        uint32_t a[2][4];
#pragma unroll
        for (int mf = 0; mf < 2; ++mf)
            ldsm_x4(a[mf][0], a[mf][1], a[mf][2], a[mf][3], aRow[mf] + gA);
        const uint32_t gB = (uint32_t)(((ks * 2 + gsel) ^ sw8) << 4);
#pragma unroll
        for (int pj = 0; pj < 4; ++pj) {
            uint32_t b0, b1, b2, b3;
            ldsm_x4(b0, b1, b2, b3, bRowOff[pj] + gB);
#pragma unroll
            for (int mf = 0; mf < 2; ++mf) {
                mma_f16(acc[mf][2 * pj],     a[mf][0], a[mf][1], a[mf][2], a[mf][3], b0, b1);
                mma_f16(acc[mf][2 * pj + 1], a[mf][0], a[mf][1], a[mf][2], a[mf][3], b2, b3);
            }
        }
    }

    // ---- mask + scale + bias (replacement: NaN-safe) ----
    const float* gbias = g_bias + (h0 + hh) * (NTOK * NTOK);
    int iRow[2][2];
    bool rOk[2][2];
#pragma unroll
    for (int mf = 0; mf < 2; ++mf) {
        iRow[mf][0] = qbase + 16 * mf + r8;
        iRow[mf][1] = iRow[mf][0] + 8;
        rOk[mf][0] = (iRow[mf][0] < NTOK);
        rOk[mf][1] = (iRow[mf][1] < NTOK);
#pragma unroll
        for (int nt = 0; nt < 8; ++nt) {
            int j0 = nt * 8 + cp2, j1 = j0 + 1;
            acc[mf][nt][0] = (rOk[mf][0] && j0 < NTOK) ? acc[mf][nt][0] * SCALE + gbias[iRow[mf][0] * NTOK + j0] : -1e30f;
            acc[mf][nt][1] = (rOk[mf][0] && j1 < NTOK) ? acc[mf][nt][1] * SCALE + gbias[iRow[mf][0] * NTOK + j1] : -1e30f;
            acc[mf][nt][2] = (rOk[mf][1] && j0 < NTOK) ? acc[mf][nt][2] * SCALE + gbias[iRow[mf][1] * NTOK + j0] : -1e30f;
            acc[mf][nt][3] = (rOk[mf][1] && j1 < NTOK) ? acc[mf][nt][3] * SCALE + gbias[iRow[mf][1] * NTOK + j1] : -1e30f;
        }
    }

    // ---- register softmax per mf (rows spread over 4-lane quads) ----
    uint32_t pa[2][4][4];
#pragma unroll
    for (int mf = 0; mf < 2; ++mf) {
        float m0 = -1e30f, m1 = -1e30f;
#pragma unroll
        for (int nt = 0; nt < 8; ++nt) {
            m0 = fmaxf(m0, fmaxf(acc[mf][nt][0], acc[mf][nt][1]));
            m1 = fmaxf(m1, fmaxf(acc[mf][nt][2], acc[mf][nt][3]));
        }
        m0 = fmaxf(m0, __shfl_xor_sync(0xFFFFFFFFu, m0, 1));
        m0 = fmaxf(m0, __shfl_xor_sync(0xFFFFFFFFu, m0, 2));
        m1 = fmaxf(m1, __shfl_xor_sync(0xFFFFFFFFu, m1, 1));
        m1 = fmaxf(m1, __shfl_xor_sync(0xFFFFFFFFu, m1, 2));

        float s0 = 0.f, s1 = 0.f;
#pragma unroll
        for (int nt = 0; nt < 8; ++nt) {
            acc[mf][nt][0] = __expf(acc[mf][nt][0] - m0); s0 += acc[mf][nt][0];
            acc[mf][nt][1] = __expf(acc[mf][nt][1] - m0); s0 += acc[mf][nt][1];
            acc[mf][nt][2] = __expf(acc[mf][nt][2] - m1); s1 += acc[mf][nt][2];
            acc[mf][nt][3] = __expf(acc[mf][nt][3] - m1); s1 += acc[mf][nt][3];
        }
        s0 += __shfl_xor_sync(0xFFFFFFFFu, s0, 1);
        s0 += __shfl_xor_sync(0xFFFFFFFFu, s0, 2);
        s1 += __shfl_xor_sync(0xFFFFFFFFu, s1, 1);
        s1 += __shfl_xor_sync(0xFFFFFFFFu, s1, 2);
        const float inv0 = 1.f / s0, inv1 = 1.f / s1;

#pragma unroll
        for (int ks = 0; ks < 4; ++ks) {
            __half2 t0 = __floats2half2_rn(acc[mf][2 * ks][0] * inv0,     acc[mf][2 * ks][1] * inv0);
            __half2 t1 = __floats2half2_rn(acc[mf][2 * ks][2] * inv1,     acc[mf][2 * ks][3] * inv1);
            __half2 t2 = __floats2half2_rn(acc[mf][2 * ks + 1][0] * inv0, acc[mf][2 * ks + 1][1] * inv0);
            __half2 t3 = __floats2half2_rn(acc[mf][2 * ks + 1][2] * inv1, acc[mf][2 * ks + 1][3] * inv1);
            pa[mf][ks][0] = *(uint32_t*)&t0;
            pa[mf][ks][1] = *(uint32_t*)&t1;
            pa[mf][ks][2] = *(uint32_t*)&t2;
            pa[mf][ks][3] = *(uint32_t*)&t3;
        }
    }

    // ---- PV from register fragments ----
    float out[2][8][4];
#pragma unroll
    for (int mf = 0; mf < 2; ++mf)
#pragma unroll
        for (int nt = 0; nt < 8; ++nt)
#pragma unroll
            for (int c = 0; c < 4; ++c) out[mf][nt][c] = 0.f;

#pragma unroll
    for (int ks = 0; ks < 4; ++ks) {
        const uint32_t vRow = vb + (uint32_t)((16 * ks + 8 * gsel + sw8) * 128);
#pragma unroll
        for (int pj = 0; pj < 4; ++pj) {
            uint32_t b0, b1, b2, b3;
            ldsm_x4_t(b0, b1, b2, b3, vRow + (uint32_t)((((2 * pj + rsel) ^ sw8) << 4)));
#pragma unroll
            for (int mf = 0; mf < 2; ++mf) {
                mma_f16(out[mf][2 * pj],     pa[mf][ks][0], pa[mf][ks][1], pa[mf][ks][2], pa[mf][ks][3], b0, b1);
                mma_f16(out[mf][2 * pj + 1], pa[mf][ks][0], pa[mf][ks][1], pa[mf][ks][2], pa[mf][ks][3], b2, b3);
            }
        }
    }

    // ---- store ----
#pragma unroll
    for (int mf = 0; mf < 2; ++mf)
#pragma unroll
        for (int nt = 0; nt < 8; ++nt) {
            int d = nt * 8 + cp2;
            if (rOk[mf][0]) {
                __half2 o = __floats2half2_rn(out[mf][nt][0], out[mf][nt][1]);
                *(__half2*)&g_B[hb + (size_t)iRow[mf][0] * DIMC + d] = o;
            }
            if (rOk[mf][1]) {
                __half2 o = __floats2half2_rn(out[mf][nt][2], out[mf][nt][3]);
                *(__half2*)&g_B[hb + (size_t)iRow[mf][1] * DIMC + d] = o;
            }
        }
}

// ---------------- launch ----------------
extern "C" void kernel_launch(void* const* d_in, const int* in_sizes, int n_in,
                              void* d_out, int out_size) {
    const float* landmark = (const float*)d_in[0];
    const float* image    = (const float*)d_in[1];
    const float* Wq = (const float*)d_in[2];
    const float* bq = (const float*)d_in[3];
    const float* Wk = (const float*)d_in[4];
    const float* bk = (const float*)d_in[5];
    const float* Wv = (const float*)d_in[6];
    const float* bv = (const float*)d_in[7];
    const float* Wo = (const float*)d_in[8];
    const float* bo = (const float*)d_in[9];
    const float* bt = (const float*)d_in[10];
    const int*   ri = (const int*)d_in[11];
    float* out = (float*)d_out;

    cudaFuncSetAttribute(gemm_qkv, cudaFuncAttributeMaxDynamicSharedMemorySize, SMEMSZ);
    cudaFuncSetAttribute(gemm_o,   cudaFuncAttributeMaxDynamicSharedMemorySize, SMEMSZ);
    cudaFuncSetAttribute(attn_mma, cudaFuncAttributeMaxDynamicSharedMemorySize, ATTN_SMEM);

    dim3 gq(DIMC / BN, MROWS / BM, 3);
    dim3 go(DIMC / BN, MROWS / BM);

    f2h_all<<<8192, 256>>>(landmark, image, Wq, Wk, Wv, Wo, bt, ri);
    gemm_qkv<<<gq, 256, SMEMSZ>>>(bq, bk, bv);
    attn_mma<<<dim3(BATCH, HEADS / HPC), 256, ATTN_SMEM>>>();
    gemm_o<<<go, 256, SMEMSZ>>>(bo, out);
}

// round 17
// speedup vs baseline: 1.1141x; 1.1141x over previous
#include <cuda_runtime.h>
#include <cuda_fp16.h>
#include <cstdint>

#define DIMC   1024
#define HEADS  16
#define NTOK   49
#define BATCH  1024
#define MROWS  (BATCH * NTOK)   // 50176
#define SCALE  0.125f

// ---------------- half scratch ----------------
__device__ __half g_A[(size_t)MROWS * DIMC];
__device__ __half g_B[(size_t)MROWS * DIMC];
__device__ __half g_Q[(size_t)MROWS * DIMC];
__device__ __half g_K[(size_t)MROWS * DIMC];
__device__ __half g_V[(size_t)MROWS * DIMC];
__device__ __half g_Wh[4 * (size_t)DIMC * DIMC];
__device__ float  g_bias[HEADS * NTOK * NTOK];

// ---------------- fused conversion: inputs + weights + bias table ----------------
__global__ void f2h_all(const float* __restrict__ a, const float* __restrict__ b,
                        const float* __restrict__ w0, const float* __restrict__ w1,
                        const float* __restrict__ w2, const float* __restrict__ w3,
                        const float* __restrict__ bt, const int* __restrict__ ri) {
    const int n4 = MROWS * DIMC / 4;
    int i = blockIdx.x * blockDim.x + threadIdx.x;
    int stride = gridDim.x * blockDim.x;
    for (int t = i; t < n4; t += stride) {
        float4 v = ((const float4*)a)[t];
        __half2 h0 = __floats2half2_rn(v.x, v.y), h1 = __floats2half2_rn(v.z, v.w);
        ((uint2*)g_A)[t] = make_uint2(*(uint32_t*)&h0, *(uint32_t*)&h1);
        v = ((const float4*)b)[t];
        h0 = __floats2half2_rn(v.x, v.y); h1 = __floats2half2_rn(v.z, v.w);
        ((uint2*)g_B)[t] = make_uint2(*(uint32_t*)&h0, *(uint32_t*)&h1);
    }
    const float* srcs[4] = {w0, w1, w2, w3};
    const int w4 = DIMC * DIMC / 4;
#pragma unroll
    for (int m = 0; m < 4; ++m) {
        const float4* src = (const float4*)srcs[m];
        uint2* dst = (uint2*)(g_Wh + (size_t)m * DIMC * DIMC);
        for (int t = i; t < w4; t += stride) {
            float4 v = src[t];
            __half2 h0 = __floats2half2_rn(v.x, v.y), h1 = __floats2half2_rn(v.z, v.w);
            dst[t] = make_uint2(*(uint32_t*)&h0, *(uint32_t*)&h1);
        }
    }
    for (int t = i; t < NTOK * NTOK; t += stride) {
        int idx = ri[t] * HEADS;
#pragma unroll
        for (int h = 0; h < HEADS; ++h)
            g_bias[h * (NTOK * NTOK) + t] = bt[idx + h];
    }
}

// ---------------- asm helpers ----------------
__device__ __forceinline__ void cp_async16(uint32_t saddr, const void* g) {
    asm volatile("cp.async.cg.shared.global [%0], [%1], 16;\n" :: "r"(saddr), "l"(g) : "memory");
}
__device__ __forceinline__ void cp_commit() { asm volatile("cp.async.commit_group;\n" ::: "memory"); }
__device__ __forceinline__ void cp_wait1() { asm volatile("cp.async.wait_group 1;\n" ::: "memory"); }
__device__ __forceinline__ void cp_wait0() { asm volatile("cp.async.wait_group 0;\n" ::: "memory"); }

__device__ __forceinline__ void mma_f16(float c[4], uint32_t a0, uint32_t a1, uint32_t a2,
                                        uint32_t a3, uint32_t b0, uint32_t b1) {
    asm volatile(
        "mma.sync.aligned.m16n8k16.row.col.f32.f16.f16.f32 "
        "{%0,%1,%2,%3}, {%4,%5,%6,%7}, {%8,%9}, {%0,%1,%2,%3};\n"
        : "+f"(c[0]), "+f"(c[1]), "+f"(c[2]), "+f"(c[3])
        : "r"(a0), "r"(a1), "r"(a2), "r"(a3), "r"(b0), "r"(b1));
}

__device__ __forceinline__ void ldsm_x4(uint32_t& r0, uint32_t& r1, uint32_t& r2, uint32_t& r3,
                                        uint32_t addr) {
    asm volatile("ldmatrix.sync.aligned.m8n8.x4.shared.b16 {%0,%1,%2,%3}, [%4];"
                 : "=r"(r0), "=r"(r1), "=r"(r2), "=r"(r3) : "r"(addr));
}
__device__ __forceinline__ void ldsm_x4_t(uint32_t& r0, uint32_t& r1, uint32_t& r2, uint32_t& r3,
                                          uint32_t addr) {
    asm volatile("ldmatrix.sync.aligned.m8n8.x4.trans.shared.b16 {%0,%1,%2,%3}, [%4];"
                 : "=r"(r0), "=r"(r1), "=r"(r2), "=r"(r3) : "r"(addr));
}

// ---------------- FP16 GEMM: 128x128 tile, 512 threads, 32x32 warp tile ----------------
#define BM 128
#define BN 128
#define BKH 64
#define NKT (DIMC / BKH)           // 16
#define TILE_A (BM * 128)          // 16384 B
#define SLOT (2 * TILE_A)
#define SMEMSZ (3 * SLOT)          // 98304 B

__device__ __forceinline__ void gemm_core(
    const __half* __restrict__ X, const __half* __restrict__ W,
    const float* __restrict__ bias, float* __restrict__ Yf, __half* __restrict__ Yh,
    int m0, int n0, uint8_t* smem)
{
    const int tid = threadIdx.x, wid = tid >> 5, lane = tid & 31;
    const int wm = wid >> 2, wn = wid & 3;        // 4x4 warp grid
    const uint32_t sbase = (uint32_t)__cvta_generic_to_shared(smem);

    float acc[2][4][4];
#pragma unroll
    for (int a = 0; a < 2; ++a)
#pragma unroll
        for (int b = 0; b < 4; ++b)
#pragma unroll
            for (int c = 0; c < 4; ++c) acc[a][b][c] = 0.f;

    const int lane_r = lane & 15;
    const int halfA  = lane >> 4;
    const int swA    = lane_r & 7;
    uint32_t offA[2];
#pragma unroll
    for (int mi = 0; mi < 2; ++mi)
        offA[mi] = (uint32_t)((wm * 32 + mi * 16 + lane_r) * 128);

    const int quad = lane >> 3;
    const int swB  = lane & 7;
    const int gselB = quad & 1;
    uint32_t offB[2];
#pragma unroll
    for (int pi = 0; pi < 2; ++pi)
        offB[pi] = (uint32_t)((wn * 32 + (2 * pi + (quad >> 1)) * 8 + (lane & 7)) * 128);

    // loader: 512 threads, each does 2 granule-pairs of A and B
    const int row = tid >> 2;           // 0..127
    const int g0 = (tid & 3) * 2;       // granules g0, g0+1
    const int swr = row & 7;
    auto load_stage = [&](int slot, int kt) {
        const __half* xa = X + (size_t)(m0 + row) * DIMC + kt * BKH;
        const __half* xb = W + (size_t)(n0 + row) * DIMC + kt * BKH;
        uint32_t sa = sbase + slot * SLOT + row * 128;
        uint32_t sb = sa + TILE_A;
#pragma unroll
        for (int q = 0; q < 2; ++q) {
            int g = g0 + q;
            uint32_t off = (uint32_t)((g ^ swr) << 4);
            cp_async16(sa + off, xa + g * 8);
            cp_async16(sb + off, xb + g * 8);
        }
        cp_commit();
    };

    load_stage(0, 0);
    load_stage(1, 1);

    const int r8 = lane >> 2, cp2 = (lane & 3) * 2;

    for (int kt = 0; kt < NKT; ++kt) {
        cp_wait1();
        __syncthreads();
        if (kt + 2 < NKT) load_stage((kt + 2) % 3, kt + 2);

        const uint32_t baseA = sbase + (kt % 3) * SLOT;
        const uint32_t baseB = baseA + TILE_A;
#pragma unroll
        for (int ks = 0; ks < 4; ++ks) {
            uint32_t a[2][4], b[2][4];
            const uint32_t gA = (uint32_t)(((ks * 2 + halfA) ^ swA) << 4);
            const uint32_t gB = (uint32_t)(((ks * 2 + gselB) ^ swB) << 4);
#pragma unroll
            for (int mi = 0; mi < 2; ++mi)
                ldsm_x4(a[mi][0], a[mi][1], a[mi][2], a[mi][3], baseA + offA[mi] + gA);
#pragma unroll
            for (int pi = 0; pi < 2; ++pi)
                ldsm_x4(b[pi][0], b[pi][1], b[pi][2], b[pi][3], baseB + offB[pi] + gB);
#pragma unroll
            for (int mi = 0; mi < 2; ++mi) {
                mma_f16(acc[mi][0], a[mi][0], a[mi][1], a[mi][2], a[mi][3], b[0][0], b[0][1]);
                mma_f16(acc[mi][1], a[mi][0], a[mi][1], a[mi][2], a[mi][3], b[0][2], b[0][3]);
                mma_f16(acc[mi][2], a[mi][0], a[mi][1], a[mi][2], a[mi][3], b[1][0], b[1][1]);
                mma_f16(acc[mi][3], a[mi][0], a[mi][1], a[mi][2], a[mi][3], b[1][2], b[1][3]);
            }
        }
    }

#pragma unroll
    for (int mi = 0; mi < 2; ++mi) {
        int r = m0 + wm * 32 + mi * 16 + r8;
#pragma unroll
        for (int ni = 0; ni < 4; ++ni) {
            int cc = n0 + wn * 32 + ni * 8 + cp2;
            float b0 = bias[cc], b1 = bias[cc + 1];
            float v0 = acc[mi][ni][0] + b0, v1 = acc[mi][ni][1] + b1;
            float v2 = acc[mi][ni][2] + b0, v3 = acc[mi][ni][3] + b1;
            if (Yf) {
                *(float2*)&Yf[(size_t)r * DIMC + cc]       = make_float2(v0, v1);
                *(float2*)&Yf[(size_t)(r + 8) * DIMC + cc] = make_float2(v2, v3);
            } else {
                __half2 h0 = __floats2half2_rn(v0, v1);
                __half2 h1 = __floats2half2_rn(v2, v3);
                *(__half2*)&Yh[(size_t)r * DIMC + cc]       = h0;
                *(__half2*)&Yh[(size_t)(r + 8) * DIMC + cc] = h1;
            }
        }
    }
}

__global__ __launch_bounds__(512, 2) void gemm_qkv(
    const float* __restrict__ bq, const float* __restrict__ bk, const float* __restrict__ bv)
{
    extern __shared__ __align__(128) uint8_t smem[];
    const int z = blockIdx.z;
    const __half* X = (z == 0) ? g_A : g_B;
    const __half* W = g_Wh + (size_t)z * DIMC * DIMC;
    __half* Yh = (z == 0) ? g_Q : (z == 1) ? g_K : g_V;
    const float* bias = (z == 0) ? bq : (z == 1) ? bk : bv;
    gemm_core(X, W, bias, nullptr, Yh, blockIdx.y * BM, blockIdx.x * BN, smem);
}

__global__ __launch_bounds__(512, 2) void gemm_o(
    const float* __restrict__ bo, float* __restrict__ out)
{
    extern __shared__ __align__(128) uint8_t smem[];
    gemm_core(g_B, g_Wh + 3 * (size_t)DIMC * DIMC, bo, out, nullptr,
              blockIdx.y * BM, blockIdx.x * BN, smem);
}

// ---------------- attention: reg-softmax + cp.async (R13 proven version) ----------------
__global__ __launch_bounds__(128) void attn_mma() {
    __shared__ __align__(128) uint8_t sQ[64 * 128];
    __shared__ __align__(128) uint8_t sK[64 * 128];
    __shared__ __align__(128) uint8_t sV[64 * 128];

    const int b = blockIdx.x, h = blockIdx.y;
    const int tid = threadIdx.x, warp = tid >> 5, lane = tid & 31;
    const size_t base = (size_t)(b * NTOK) * DIMC + h * 64;

    const uint32_t qb = (uint32_t)__cvta_generic_to_shared(sQ);
    const uint32_t kb = (uint32_t)__cvta_generic_to_shared(sK);
    const uint32_t vb = (uint32_t)__cvta_generic_to_shared(sV);

    for (int t = tid; t < NTOK * 8; t += 128) {
        int r = t >> 3, g = t & 7;
        uint32_t off = (uint32_t)(r * 128 + ((g ^ (r & 7)) << 4));
        const size_t gsrc = base + (size_t)r * DIMC + g * 8;
        cp_async16(qb + off, &g_Q[gsrc]);
        cp_async16(kb + off, &g_K[gsrc]);
        cp_async16(vb + off, &g_V[gsrc]);
    }
    for (int t = tid; t < 15 * 8; t += 128) {
        int r = NTOK + (t >> 3), g = t & 7;
        uint32_t off = (uint32_t)(r * 128 + ((g ^ (r & 7)) << 4));
        *(uint4*)(sV + off) = make_uint4(0, 0, 0, 0);
    }
    cp_commit();
    cp_wait0();
    __syncthreads();

    const int lane_r = lane & 15, halfA = lane >> 4;
    const int quad = lane >> 3, gsel = quad & 1, rsel = quad >> 1;
    const int r8 = lane >> 2, cp2 = (lane & 3) * 2;
    const int swA = lane_r & 7, sw8 = lane & 7;

    float acc[8][4];
#pragma unroll
    for (int nt = 0; nt < 8; ++nt)
#pragma unroll
        for (int c = 0; c < 4; ++c) acc[nt][c] = 0.f;

    const uint32_t aRowOff = qb + (uint32_t)((16 * warp + lane_r) * 128);
    uint32_t bRowOff[4];
#pragma unroll
    for (int pj = 0; pj < 4; ++pj)
        bRowOff[pj] = kb + (uint32_t)((16 * pj + rsel * 8 + sw8) * 128);

#pragma unroll
    for (int ks = 0; ks < 4; ++ks) {
        uint32_t a0, a1, a2, a3;
        ldsm_x4(a0, a1, a2, a3, aRowOff + (uint32_t)(((ks * 2 + halfA) ^ swA) << 4));
        const uint32_t gB = (uint32_t)(((ks * 2 + gsel) ^ sw8) << 4);
#pragma unroll
        for (int pj = 0; pj < 4; ++pj) {
            uint32_t b0, b1, b2, b3;
            ldsm_x4(b0, b1, b2, b3, bRowOff[pj] + gB);
            mma_f16(acc[2 * pj],     a0, a1, a2, a3, b0, b1);
            mma_f16(acc[2 * pj + 1], a0, a1, a2, a3, b2, b3);
        }
    }

    const float* gbias = g_bias + h * (NTOK * NTOK);
    const int i0 = 16 * warp + r8, i1 = i0 + 8;
    const bool ri0 = (i0 < NTOK), ri1 = (i1 < NTOK);
#pragma unroll
    for (int nt = 0; nt < 8; ++nt) {
        int j0 = nt * 8 + cp2, j1 = j0 + 1;
        acc[nt][0] = (ri0 && j0 < NTOK) ? acc[nt][0] * SCALE + gbias[i0 * NTOK + j0] : -1e30f;
        acc[nt][1] = (ri0 && j1 < NTOK) ? acc[nt][1] * SCALE + gbias[i0 * NTOK + j1] : -1e30f;
        acc[nt][2] = (ri1 && j0 < NTOK) ? acc[nt][2] * SCALE + gbias[i1 * NTOK + j0] : -1e30f;
        acc[nt][3] = (ri1 && j1 < NTOK) ? acc[nt][3] * SCALE + gbias[i1 * NTOK + j1] : -1e30f;
    }

    float m0 = -1e30f, m1 = -1e30f;
#pragma unroll
    for (int nt = 0; nt < 8; ++nt) {
        m0 = fmaxf(m0, fmaxf(acc[nt][0], acc[nt][1]));
        m1 = fmaxf(m1, fmaxf(acc[nt][2], acc[nt][3]));
    }
    m0 = fmaxf(m0, __shfl_xor_sync(0xFFFFFFFFu, m0, 1));
    m0 = fmaxf(m0, __shfl_xor_sync(0xFFFFFFFFu, m0, 2));
    m1 = fmaxf(m1, __shfl_xor_sync(0xFFFFFFFFu, m1, 1));
    m1 = fmaxf(m1, __shfl_xor_sync(0xFFFFFFFFu, m1, 2));

    float s0 = 0.f, s1 = 0.f;
#pragma unroll
    for (int nt = 0; nt < 8; ++nt) {
        acc[nt][0] = __expf(acc[nt][0] - m0); s0 += acc[nt][0];
        acc[nt][1] = __expf(acc[nt][1] - m0); s0 += acc[nt][1];
        acc[nt][2] = __expf(acc[nt][2] - m1); s1 += acc[nt][2];
        acc[nt][3] = __expf(acc[nt][3] - m1); s1 += acc[nt][3];
    }
    s0 += __shfl_xor_sync(0xFFFFFFFFu, s0, 1);
    s0 += __shfl_xor_sync(0xFFFFFFFFu, s0, 2);
    s1 += __shfl_xor_sync(0xFFFFFFFFu, s1, 1);
    s1 += __shfl_xor_sync(0xFFFFFFFFu, s1, 2);
    const float inv0 = 1.f / s0, inv1 = 1.f / s1;

    uint32_t pa[4][4];
#pragma unroll
    for (int ks = 0; ks < 4; ++ks) {
        __half2 t0 = __floats2half2_rn(acc[2 * ks][0] * inv0,     acc[2 * ks][1] * inv0);
        __half2 t1 = __floats2half2_rn(acc[2 * ks][2] * inv1,     acc[2 * ks][3] * inv1);
        __half2 t2 = __floats2half2_rn(acc[2 * ks + 1][0] * inv0, acc[2 * ks + 1][1] * inv0);
        __half2 t3 = __floats2half2_rn(acc[2 * ks + 1][2] * inv1, acc[2 * ks + 1][3] * inv1);
        pa[ks][0] = *(uint32_t*)&t0;
        pa[ks][1] = *(uint32_t*)&t1;
        pa[ks][2] = *(uint32_t*)&t2;
        pa[ks][3] = *(uint32_t*)&t3;
    }

    float out[8][4];
#pragma unroll
    for (int nt = 0; nt < 8; ++nt)
#pragma unroll
        for (int c = 0; c < 4; ++c) out[nt][c] = 0.f;

#pragma unroll
    for (int ks = 0; ks < 4; ++ks) {
        const uint32_t vRow = vb + (uint32_t)((16 * ks + 8 * gsel + sw8) * 128);
#pragma unroll
        for (int pj = 0; pj < 4; ++pj) {
            uint32_t b0, b1, b2, b3;
            ldsm_x4_t(b0, b1, b2, b3, vRow + (uint32_t)((((2 * pj + rsel) ^ sw8) << 4)));
            mma_f16(out[2 * pj],     pa[ks][0], pa[ks][1], pa[ks][2], pa[ks][3], b0, b1);
            mma_f16(out[2 * pj + 1], pa[ks][0], pa[ks][1], pa[ks][2], pa[ks][3], b2, b3);
        }
    }

#pragma unroll
    for (int nt = 0; nt < 8; ++nt) {
        int d = nt * 8 + cp2;
        if (ri0) {
            __half2 o = __floats2half2_rn(out[nt][0], out[nt][1]);
            *(__half2*)&g_B[base + (size_t)i0 * DIMC + d] = o;
        }
        if (ri1) {
            __half2 o = __floats2half2_rn(out[nt][2], out[nt][3]);
            *(__half2*)&g_B[base + (size_t)i1 * DIMC + d] = o;
        }
    }
}

// ---------------- launch ----------------
extern "C" void kernel_launch(void* const* d_in, const int* in_sizes, int n_in,
                              void* d_out, int out_size) {
    const float* landmark = (const float*)d_in[0];
    const float* image    = (const float*)d_in[1];
    const float* Wq = (const float*)d_in[2];
    const float* bq = (const float*)d_in[3];
    const float* Wk = (const float*)d_in[4];
    const float* bk = (const float*)d_in[5];
    const float* Wv = (const float*)d_in[6];
    const float* bv = (const float*)d_in[7];
    const float* Wo = (const float*)d_in[8];
    const float* bo = (const float*)d_in[9];
    const float* bt = (const float*)d_in[10];
    const int*   ri = (const int*)d_in[11];
    float* out = (float*)d_out;

    cudaFuncSetAttribute(gemm_qkv, cudaFuncAttributeMaxDynamicSharedMemorySize, SMEMSZ);
    cudaFuncSetAttribute(gemm_o,   cudaFuncAttributeMaxDynamicSharedMemorySize, SMEMSZ);

    dim3 gq(DIMC / BN, MROWS / BM, 3);
    dim3 go(DIMC / BN, MROWS / BM);

    f2h_all<<<8192, 256>>>(landmark, image, Wq, Wk, Wv, Wo, bt, ri);
    gemm_qkv<<<gq, 512, SMEMSZ>>>(bq, bk, bv);
    attn_mma<<<dim3(BATCH, HEADS), 128>>>();
    gemm_o<<<go, 512, SMEMSZ>>>(bo, out);
}